// round 16
// baseline (speedup 1.0000x reference)
#include <cuda_runtime.h>
#include <cuda_fp16.h>
#include <math.h>
#include <stdint.h>

#define NE 8
#define DIM 1024
#define IDIM 2048
#define NTOK 4096
#define ESTRIDE 4096

// ---------------- device scratch ----------------
__device__ int   g_count[NE];
__device__ int   g_rows[NE * ESTRIDE];
__device__ float g_w[NE * ESTRIDE];
// flags: [0]=route [1]=x [2]=zero [4+e]=wgu [12+e]=up [20+e]=wd
__device__ int   g_flags[28];
__device__ __half g_xh[NTOK * DIM];
__device__ __half g_wg[NE * DIM * IDIM];   // [e][d][i]  (K=d rows, N=i contiguous)
__device__ __half g_wu[NE * DIM * IDIM];
__device__ __half g_wd[NE * IDIM * DIM];   // [e][i][d]  (K=i rows, N=d contiguous)
__device__ __half g_hh[(size_t)NE * ESTRIDE * IDIM];

// ---------------- helpers ----------------
__device__ __forceinline__ uint32_t smem_u32(const void* p) {
    uint32_t a;
    asm("{ .reg .u64 t; cvta.to.shared.u64 t, %1; cvt.u32.u64 %0, t; }"
        : "=r"(a) : "l"(p));
    return a;
}

#define LDSM4(r0, r1, r2, r3, addr)                                          \
    asm volatile("ldmatrix.sync.aligned.m8n8.x4.shared.b16 {%0,%1,%2,%3}, [%4];" \
                 : "=r"(r0), "=r"(r1), "=r"(r2), "=r"(r3) : "r"(addr))

#define LDSM4T(r0, r1, r2, r3, addr)                                         \
    asm volatile("ldmatrix.sync.aligned.m8n8.x4.trans.shared.b16 {%0,%1,%2,%3}, [%4];" \
                 : "=r"(r0), "=r"(r1), "=r"(r2), "=r"(r3) : "r"(addr))

#define MMA16816(c, a, b)                                                    \
    asm volatile("mma.sync.aligned.m16n8k16.row.col.f32.f16.f16.f32 "        \
                 "{%0,%1,%2,%3},{%4,%5,%6,%7},{%8,%9},{%0,%1,%2,%3};"        \
                 : "+f"((c)[0]), "+f"((c)[1]), "+f"((c)[2]), "+f"((c)[3])    \
                 : "r"((a)[0]), "r"((a)[1]), "r"((a)[2]), "r"((a)[3]),       \
                   "r"((b)[0]), "r"((b)[1]))

#define CPA16(dst, src, sz)                                                  \
    asm volatile("cp.async.cg.shared.global [%0], [%1], 16, %2;"             \
                 :: "r"(dst), "l"(src), "r"(sz) : "memory")
#define CP_COMMIT() asm volatile("cp.async.commit_group;" ::: "memory")
#define CP_WAIT(n)  asm volatile("cp.async.wait_group %0;" ::"n"(n) : "memory")

#define REDV2(ptr, a, b)                                                     \
    asm volatile("red.global.add.v2.f32 [%0], {%1, %2};"                     \
                 :: "l"(ptr), "f"(a), "f"(b) : "memory")

// swizzles: 16B chunks within a row
__device__ __forceinline__ uint32_t SWZ8(uint32_t row, uint32_t ch) {   // 128B rows
    return row * 128 + ((ch ^ (row & 7)) << 4);
}
__device__ __forceinline__ uint32_t SWZ16(uint32_t row, uint32_t ch) {  // 256B rows
    return row * 256 + (((ch & 8) | ((ch ^ row) & 7)) << 4);
}

__device__ __forceinline__ void conv_chunk(const float* __restrict__ in,
                                           __half* __restrict__ out,
                                           int j0, int j1, int stride) {
    for (int j = j0; j < j1; j += stride) {
        float4 v = reinterpret_cast<const float4*>(in)[j];
        __half hv[4] = {__float2half_rn(v.x), __float2half_rn(v.y),
                        __float2half_rn(v.z), __float2half_rn(v.w)};
        reinterpret_cast<uint2*>(out)[j] = *reinterpret_cast<uint2*>(hv);
    }
}

__device__ __forceinline__ void signal(int idx) {
    __threadfence();
    __syncthreads();
    if (threadIdx.x == 0) atomicAdd(&g_flags[idx], 1);
}

// =======================================================================
// single fused kernel — grid sections by blockIdx.x (bid dispatch order):
//  route(512) | conv_x(1024) | zero(512) | wg/wu conv expert-major(8192) |
//  up MMA + wd conv(8448) | down MMA(2048)
// =======================================================================
#define B_X0    512
#define B_ZERO0 1536
#define B_W0    2048
#define B_UP0   10240
#define B_DN0   18688
#define B_TOT   20736

// smem stage layouts (Kc=64, depth-3); both roles use 98304 bytes
#define U_A   0
#define U_BG  16384
#define U_BU  24576
#define U_STAGE 32768
#define D_A   0
#define D_B   16384
#define D_STAGE 32768
#define F_SMEM (3 * 32768)

#define UP_X 33                      // 32 m-tiles + 1 wd-converter slice

__global__ __launch_bounds__(256, 2)
void mob_kernel(const float* __restrict__ hs,
                const float* __restrict__ Wc,
                const float* __restrict__ bc,
                const float* __restrict__ Wg,
                const float* __restrict__ Wu,
                const float* __restrict__ Wd,
                float* __restrict__ out, int out_n) {
    extern __shared__ char dsm[];
    __shared__ int stok[128];

    int b = blockIdx.x, tid = threadIdx.x;
    uint32_t sb = smem_u32(dsm);
    int wid = tid >> 5, l = tid & 31;

    if (b < B_X0) {
        // ---------------- ROUTE ----------------
        int gwarp = (b * 256 + tid) >> 5;
        int lane = tid & 31;
        const float* xr = hs + (size_t)gwarp * DIM;
        float acc[NE];
#pragma unroll
        for (int e = 0; e < NE; e++) acc[e] = 0.0f;
        for (int d = lane; d < DIM; d += 32) {
            float xv = xr[d];
#pragma unroll
            for (int e = 0; e < NE; e++) acc[e] += xv * Wc[e * DIM + d];
        }
#pragma unroll
        for (int e = 0; e < NE; e++)
#pragma unroll
            for (int off = 16; off > 0; off >>= 1)
                acc[e] += __shfl_xor_sync(0xffffffffu, acc[e], off);
        if (lane == 0) {
            float conf[NE];
#pragma unroll
            for (int e = 0; e < NE; e++)
                conf[e] = 1.0f / (1.0f + expf(-(acc[e] + bc[e])));
            int i0 = 0;
#pragma unroll
            for (int e = 1; e < NE; e++) if (conf[e] > conf[i0]) i0 = e;
            int i1 = -1;
#pragma unroll
            for (int e = 0; e < NE; e++) {
                if (e == i0) continue;
                if (i1 < 0 || conf[e] > conf[i1]) i1 = e;
            }
            float v0 = conf[i0], v1 = conf[i1];
            float w0 = 1.0f / (1.0f + expf(v1 - v0));
            float w1 = 1.0f / (1.0f + expf(v0 - v1));
            int p0 = atomicAdd(&g_count[i0], 1);
            g_rows[i0 * ESTRIDE + p0] = gwarp;
            g_w[i0 * ESTRIDE + p0] = w0;
            int p1 = atomicAdd(&g_count[i1], 1);
            g_rows[i1 * ESTRIDE + p1] = gwarp;
            g_w[i1 * ESTRIDE + p1] = w1;
        }
        signal(0);

    } else if (b < B_ZERO0) {
        // ---------------- CONV X ----------------
        int cb = b - B_X0;
        conv_chunk(hs, g_xh, cb * 256 + tid, NTOK * DIM / 4, 1024 * 256);
        signal(1);

    } else if (b < B_W0) {
        // ---------------- ZERO OUT ----------------
        int zb = b - B_ZERO0;
        int n4 = out_n / 4;
        float4 z = make_float4(0.f, 0.f, 0.f, 0.f);
        for (int j = zb * 256 + tid; j < n4; j += 512 * 256)
            reinterpret_cast<float4*>(out)[j] = z;
        signal(2);

    } else if (b < B_UP0) {
        // ---------------- WG/WU CONV (expert-major) ----------------
        int wb = b - B_W0;
        int e = wb >> 10, within = wb & 1023;     // 1024 blocks per expert
        const int PER = (DIM * IDIM / 4) / 512;   // 1024 uint4 per block
        size_t eo = (size_t)e * DIM * IDIM;
        if (within < 512) {
            int s = within;
            conv_chunk(Wg + eo, g_wg + eo, s * PER + tid, (s + 1) * PER, 256);
        } else {
            int s = within - 512;
            conv_chunk(Wu + eo, g_wu + eo, s * PER + tid, (s + 1) * PER, 256);
        }
        signal(4 + e);

    } else if (b < B_DN0) {
        // ---------------- UP role ----------------
        int u = b - B_UP0;
        int ux = u % UP_X, rem = u / UP_X;
        int uy = rem % 32, uz = rem / 32;   // uz = expert

        if (ux == 32) {
            // Wd fp32->fp16 converter slice (32 per expert) — no waits
            const int per = (IDIM * DIM / 4) / 32;   // 16384
            size_t eo = (size_t)uz * IDIM * DIM;
            conv_chunk(Wd + eo, g_wd + eo, uy * per + tid, (uy + 1) * per, 256);
            signal(20 + uz);
            return;
        }

        int e = uz;
        // wait: route + x + this expert's wg/wu conversion
        if (tid == 0) {
            volatile int* f = g_flags;
            while (f[0] < 512 || f[1] < 1024 || f[4 + e] < 1024) __nanosleep(200);
        }
        __syncthreads();

        int m0 = ux * 128, n0 = uy * 64;
        int ne = g_count[e];
        if (m0 >= ne) { signal(12 + e); return; }
        if (tid < 128) stok[tid] = (m0 + tid < ne) ? g_rows[e * ESTRIDE + m0 + tid] : -1;
        __syncthreads();

        int wm = wid & 3, wn = wid >> 2;

        const __half* WG = g_wg + (size_t)e * DIM * IDIM;
        const __half* WU = g_wu + (size_t)e * DIM * IDIM;

        int lrow = tid >> 3, lch = tid & 7;
        int lar = (l & 7) + 8 * ((l >> 3) & 1);
        int la_ch = l >> 4;
        int ktr = (l & 7) + 8 * ((l >> 3) & 1);
        int ntc = l >> 4;

        float cg[2][4][4], cu[2][4][4];
#pragma unroll
        for (int i = 0; i < 2; i++)
#pragma unroll
            for (int j = 0; j < 4; j++)
#pragma unroll
                for (int q = 0; q < 4; q++) { cg[i][j][q] = 0.f; cu[i][j][q] = 0.f; }

        const int NK = DIM / 64;

        auto load_stage = [&](int kc, int s) {
            uint32_t st = sb + s * U_STAGE;
            int k0 = kc * 64;
#pragma unroll
            for (int it = 0; it < 4; it++) {
                int row = lrow + it * 32;
                int tok = stok[row];
                uint32_t sz = (tok >= 0) ? 16u : 0u;
                size_t go = (tok >= 0) ? ((size_t)tok * DIM + k0 + lch * 8) : 0;
                CPA16(st + U_A + SWZ8(row, lch), g_xh + go, sz);
            }
#pragma unroll
            for (int it = 0; it < 2; it++) {
                int row = lrow + it * 32;     // k row
                size_t go = (size_t)(k0 + row) * IDIM + n0 + lch * 8;
                uint32_t so = SWZ8(row, lch);
                CPA16(st + U_BG + so, WG + go, 16u);
                CPA16(st + U_BU + so, WU + go, 16u);
            }
            CP_COMMIT();
        };

        load_stage(0, 0);
        load_stage(1, 1);

        int s_cur = 0;
        for (int kc = 0; kc < NK; kc++) {
            if (kc + 2 < NK) {
                int s2 = s_cur + 2; if (s2 >= 3) s2 -= 3;
                load_stage(kc + 2, s2);
                CP_WAIT(2);
            } else if (kc + 1 < NK) {
                CP_WAIT(1);
            } else {
                CP_WAIT(0);
            }
            __syncthreads();

            uint32_t st = sb + s_cur * U_STAGE;
#pragma unroll
            for (int ks = 0; ks < 4; ks++) {
                uint32_t ah[2][4];
#pragma unroll
                for (int mf = 0; mf < 2; mf++) {
                    uint32_t row = wm * 32 + mf * 16 + lar;
                    LDSM4(ah[mf][0], ah[mf][1], ah[mf][2], ah[mf][3],
                          st + U_A + SWZ8(row, 2 * ks + la_ch));
                }
#pragma unroll
                for (int p = 0; p < 2; p++) {
                    uint32_t krow = ks * 16 + ktr;
                    uint32_t nch = wn * 4 + 2 * p + ntc;
                    uint32_t bg[2][2], bu[2][2];
                    LDSM4T(bg[0][0], bg[0][1], bg[1][0], bg[1][1],
                           st + U_BG + SWZ8(krow, nch));
                    LDSM4T(bu[0][0], bu[0][1], bu[1][0], bu[1][1],
                           st + U_BU + SWZ8(krow, nch));
#pragma unroll
                    for (int mf = 0; mf < 2; mf++)
#pragma unroll
                        for (int q = 0; q < 2; q++) {
                            int nf = 2 * p + q;
                            MMA16816(cg[mf][nf], ah[mf], bg[q]);
                            MMA16816(cu[mf][nf], ah[mf], bu[q]);
                        }
                }
            }
            __syncthreads();
            if (++s_cur == 3) s_cur = 0;
        }

        __half* hh = g_hh + (size_t)e * ESTRIDE * IDIM;
#pragma unroll
        for (int mf = 0; mf < 2; mf++) {
            int r_lo = m0 + wm * 32 + mf * 16 + (l >> 2);
#pragma unroll
            for (int nf = 0; nf < 4; nf++) {
                int col = n0 + wn * 32 + nf * 8 + 2 * (l & 3);
#pragma unroll
                for (int half_ = 0; half_ < 2; half_++) {
                    int r = r_lo + half_ * 8;
                    if (r >= ne) continue;
                    float gv0 = cg[mf][nf][half_ * 2 + 0], gv1 = cg[mf][nf][half_ * 2 + 1];
                    float uv0 = cu[mf][nf][half_ * 2 + 0], uv1 = cu[mf][nf][half_ * 2 + 1];
                    float h0 = uv0 * gv0 / (1.0f + expf(-gv0));
                    float h1 = uv1 * gv1 / (1.0f + expf(-gv1));
                    __half ph[2] = {__float2half_rn(h0), __float2half_rn(h1)};
                    *reinterpret_cast<uint32_t*>(hh + (size_t)r * IDIM + col) =
                        *reinterpret_cast<uint32_t*>(ph);
                }
            }
        }
        signal(12 + e);

    } else {
        // ---------------- DOWN role ----------------
        int d = b - B_DN0;
        int dx = d % 32, rem = d / 32;
        int dy = rem % 8, dz = rem / 8;
        int e = dz;

        // wait: expert e's up tiles + Wd slice + out zeroed
        if (tid == 0) {
            volatile int* f = g_flags;
            while (f[12 + e] < 1024 || f[20 + e] < 32 || f[2] < 512) __nanosleep(200);
        }
        __syncthreads();

        int m0 = dx * 128, n0 = dy * 128;
        int ne = g_count[e];
        if (m0 >= ne) return;

        int wm = wid & 3, wn = wid >> 2;

        const __half* AH = g_hh + (size_t)e * ESTRIDE * IDIM;
        const __half* B  = g_wd + (size_t)e * IDIM * DIM;

        int lrow = tid >> 3, lch = tid & 7;
        int lrow2 = tid >> 4, lch2 = tid & 15;

        int lar = (l & 7) + 8 * ((l >> 3) & 1);
        int la_ch = l >> 4;
        int ktr = (l & 7) + 8 * ((l >> 3) & 1);
        int ntc = l >> 4;

        float c[2][8][4];
#pragma unroll
        for (int i = 0; i < 2; i++)
#pragma unroll
            for (int j = 0; j < 8; j++)
#pragma unroll
                for (int q = 0; q < 4; q++) c[i][j][q] = 0.f;

        const int NK = IDIM / 64;

        auto load_stage = [&](int kc, int s) {
            uint32_t st = sb + s * D_STAGE;
            int k0 = kc * 64;
#pragma unroll
            for (int it = 0; it < 4; it++) {
                int row = lrow + it * 32;
                uint32_t sz = (m0 + row < ne) ? 16u : 0u;
                size_t ga = (m0 + row < ne) ? ((size_t)(m0 + row) * IDIM + k0 + lch * 8) : 0;
                CPA16(st + D_A + SWZ8(row, lch), AH + ga, sz);
            }
#pragma unroll
            for (int it = 0; it < 4; it++) {
                int row = lrow2 + it * 16;    // k row
                size_t gb = (size_t)(k0 + row) * DIM + n0 + lch2 * 8;
                CPA16(st + D_B + SWZ16(row, lch2), B + gb, 16u);
            }
            CP_COMMIT();
        };

        load_stage(0, 0);
        load_stage(1, 1);

        int s_cur = 0;
        for (int kc = 0; kc < NK; kc++) {
            if (kc + 2 < NK) {
                int s2 = s_cur + 2; if (s2 >= 3) s2 -= 3;
                load_stage(kc + 2, s2);
                CP_WAIT(2);
            } else if (kc + 1 < NK) {
                CP_WAIT(1);
            } else {
                CP_WAIT(0);
            }
            __syncthreads();

            uint32_t st = sb + s_cur * D_STAGE;
#pragma unroll
            for (int ks = 0; ks < 4; ks++) {
                uint32_t ah[2][4];
#pragma unroll
                for (int mf = 0; mf < 2; mf++) {
                    uint32_t row = wm * 32 + mf * 16 + lar;
                    LDSM4(ah[mf][0], ah[mf][1], ah[mf][2], ah[mf][3],
                          st + D_A + SWZ8(row, 2 * ks + la_ch));
                }
#pragma unroll
                for (int p = 0; p < 4; p++) {
                    uint32_t krow = ks * 16 + ktr;
                    uint32_t nch = wn * 8 + 2 * p + ntc;
                    uint32_t bh[2][2];
                    LDSM4T(bh[0][0], bh[0][1], bh[1][0], bh[1][1],
                           st + D_B + SWZ16(krow, nch));
#pragma unroll
                    for (int mf = 0; mf < 2; mf++)
#pragma unroll
                        for (int q = 0; q < 2; q++)
                            MMA16816(c[mf][2 * p + q], ah[mf], bh[q]);
                }
            }
            __syncthreads();
            if (++s_cur == 3) s_cur = 0;
        }

#pragma unroll
        for (int mf = 0; mf < 2; mf++) {
            int r_lo = m0 + wm * 32 + mf * 16 + (l >> 2);
#pragma unroll
            for (int half_ = 0; half_ < 2; half_++) {
                int r = r_lo + half_ * 8;
                if (r >= ne) continue;
                int   t = g_rows[e * ESTRIDE + r];
                float w = g_w[e * ESTRIDE + r];
                float* op = out + (size_t)t * DIM;
#pragma unroll
                for (int nf = 0; nf < 8; nf++) {
                    int col = n0 + wn * 64 + nf * 8 + 2 * (l & 3);
                    REDV2(op + col, w * c[mf][nf][half_ * 2 + 0],
                                    w * c[mf][nf][half_ * 2 + 1]);
                }
            }
        }
    }
}

// ---------------- launcher ----------------
extern "C" void kernel_launch(void* const* d_in, const int* in_sizes, int n_in,
                              void* d_out, int out_size) {
    const float* hs = (const float*)d_in[0];
    const float* Wc = (const float*)d_in[1];
    const float* bc = (const float*)d_in[2];
    const float* Wg = (const float*)d_in[3];
    const float* Wu = (const float*)d_in[4];
    const float* Wd = (const float*)d_in[5];
    float* out = (float*)d_out;

    cudaFuncSetAttribute(mob_kernel, cudaFuncAttributeMaxDynamicSharedMemorySize, F_SMEM);

    void* p;
    cudaGetSymbolAddress(&p, g_count);
    cudaMemsetAsync(p, 0, NE * sizeof(int));
    cudaGetSymbolAddress(&p, g_flags);
    cudaMemsetAsync(p, 0, 28 * sizeof(int));

    mob_kernel<<<B_TOT, 256, F_SMEM>>>(hs, Wc, bc, Wg, Wu, Wd, out, out_size);
}

// round 17
// speedup vs baseline: 1.7593x; 1.7593x over previous
#include <cuda_runtime.h>
#include <cuda_fp16.h>
#include <math.h>
#include <stdint.h>

#define NE 8
#define DIM 1024
#define IDIM 2048
#define NTOK 4096
#define ESTRIDE 4096

// ---------------- device scratch ----------------
__device__ int   g_count[NE];
__device__ int   g_rows[NE * ESTRIDE];
__device__ float g_w[NE * ESTRIDE];
__device__ int   g_up_done[NE];
__device__ int   g_wd_done[NE];
__device__ __half g_xh[NTOK * DIM];
__device__ __half g_wg[NE * DIM * IDIM];   // [e][d][i]  (K=d rows, N=i contiguous)
__device__ __half g_wu[NE * DIM * IDIM];
__device__ __half g_wd[NE * IDIM * DIM];   // [e][i][d]  (K=i rows, N=d contiguous)
__device__ __half g_hh[(size_t)NE * ESTRIDE * IDIM];

// ---------------- helpers ----------------
__device__ __forceinline__ uint32_t smem_u32(const void* p) {
    uint32_t a;
    asm("{ .reg .u64 t; cvta.to.shared.u64 t, %1; cvt.u32.u64 %0, t; }"
        : "=r"(a) : "l"(p));
    return a;
}

#define LDSM4(r0, r1, r2, r3, addr)                                          \
    asm volatile("ldmatrix.sync.aligned.m8n8.x4.shared.b16 {%0,%1,%2,%3}, [%4];" \
                 : "=r"(r0), "=r"(r1), "=r"(r2), "=r"(r3) : "r"(addr))

#define LDSM4T(r0, r1, r2, r3, addr)                                         \
    asm volatile("ldmatrix.sync.aligned.m8n8.x4.trans.shared.b16 {%0,%1,%2,%3}, [%4];" \
                 : "=r"(r0), "=r"(r1), "=r"(r2), "=r"(r3) : "r"(addr))

#define MMA16816(c, a, b)                                                    \
    asm volatile("mma.sync.aligned.m16n8k16.row.col.f32.f16.f16.f32 "        \
                 "{%0,%1,%2,%3},{%4,%5,%6,%7},{%8,%9},{%0,%1,%2,%3};"        \
                 : "+f"((c)[0]), "+f"((c)[1]), "+f"((c)[2]), "+f"((c)[3])    \
                 : "r"((a)[0]), "r"((a)[1]), "r"((a)[2]), "r"((a)[3]),       \
                   "r"((b)[0]), "r"((b)[1]))

#define CPA16(dst, src, sz)                                                  \
    asm volatile("cp.async.cg.shared.global [%0], [%1], 16, %2;"             \
                 :: "r"(dst), "l"(src), "r"(sz) : "memory")
#define CP_COMMIT() asm volatile("cp.async.commit_group;" ::: "memory")
#define CP_WAIT(n)  asm volatile("cp.async.wait_group %0;" ::"n"(n) : "memory")

#define REDV2(ptr, a, b)                                                     \
    asm volatile("red.global.add.v2.f32 [%0], {%1, %2};"                     \
                 :: "l"(ptr), "f"(a), "f"(b) : "memory")

// swizzles: 16B chunks within a row
__device__ __forceinline__ uint32_t SWZ8(uint32_t row, uint32_t ch) {   // 128B rows
    return row * 128 + ((ch ^ (row & 7)) << 4);
}
__device__ __forceinline__ uint32_t SWZ16(uint32_t row, uint32_t ch) {  // 256B rows
    return row * 256 + (((ch & 8) | ((ch ^ row) & 7)) << 4);
}

__device__ __forceinline__ void conv_chunk(const float* __restrict__ in,
                                           __half* __restrict__ out,
                                           int j0, int j1, int stride) {
    for (int j = j0; j < j1; j += stride) {
        float4 v = reinterpret_cast<const float4*>(in)[j];
        __half hv[4] = {__float2half_rn(v.x), __float2half_rn(v.y),
                        __float2half_rn(v.z), __float2half_rn(v.w)};
        reinterpret_cast<uint2*>(out)[j] = *reinterpret_cast<uint2*>(hv);
    }
}

// MLP=4 batched converter: exactly 4 grid-stride iterations, loads issued first
__device__ __forceinline__ void conv4(const float* __restrict__ in,
                                      __half* __restrict__ out,
                                      int base, int stride) {
    float4 v[4];
#pragma unroll
    for (int u = 0; u < 4; u++)
        v[u] = reinterpret_cast<const float4*>(in)[base + u * stride];
#pragma unroll
    for (int u = 0; u < 4; u++) {
        __half hv[4] = {__float2half_rn(v[u].x), __float2half_rn(v[u].y),
                        __float2half_rn(v[u].z), __float2half_rn(v[u].w)};
        reinterpret_cast<uint2*>(out)[base + u * stride] =
            *reinterpret_cast<uint2*>(hv);
    }
}

// =======================================================================
// fused prologue: [conv wg | conv wu | conv_x | route | zero]
// =======================================================================
#define NB_W    4096
#define NB_CONV 1024
#define NB_ROUTE 512
#define NB_ZERO 512
#define NB_TOTAL (2 * NB_W + NB_CONV + NB_ROUTE + NB_ZERO)

__device__ __forceinline__ void do_route(const float* x, const float* Wc,
                                         const float* bc, int rb, int tid) {
    int gwarp = (rb * 256 + tid) >> 5;
    int lane = tid & 31;
    const float* xr = x + (size_t)gwarp * DIM;
    float acc[NE];
#pragma unroll
    for (int e = 0; e < NE; e++) acc[e] = 0.0f;
    for (int d = lane; d < DIM; d += 32) {
        float xv = xr[d];
#pragma unroll
        for (int e = 0; e < NE; e++) acc[e] += xv * Wc[e * DIM + d];
    }
#pragma unroll
    for (int e = 0; e < NE; e++)
#pragma unroll
        for (int off = 16; off > 0; off >>= 1)
            acc[e] += __shfl_xor_sync(0xffffffffu, acc[e], off);
    if (lane == 0) {
        float conf[NE];
#pragma unroll
        for (int e = 0; e < NE; e++)
            conf[e] = 1.0f / (1.0f + expf(-(acc[e] + bc[e])));
        int i0 = 0;
#pragma unroll
        for (int e = 1; e < NE; e++) if (conf[e] > conf[i0]) i0 = e;
        int i1 = -1;
#pragma unroll
        for (int e = 0; e < NE; e++) {
            if (e == i0) continue;
            if (i1 < 0 || conf[e] > conf[i1]) i1 = e;
        }
        float v0 = conf[i0], v1 = conf[i1];
        float w0 = 1.0f / (1.0f + expf(v1 - v0));
        float w1 = 1.0f / (1.0f + expf(v0 - v1));
        int p0 = atomicAdd(&g_count[i0], 1);
        g_rows[i0 * ESTRIDE + p0] = gwarp;
        g_w[i0 * ESTRIDE + p0] = w0;
        int p1 = atomicAdd(&g_count[i1], 1);
        g_rows[i1 * ESTRIDE + p1] = gwarp;
        g_w[i1 * ESTRIDE + p1] = w1;
    }
}

__global__ __launch_bounds__(256)
void prologue_kernel(const float* __restrict__ hs,
                     const float* __restrict__ Wc,
                     const float* __restrict__ bc,
                     const float* __restrict__ Wg,
                     const float* __restrict__ Wu,
                     float* __restrict__ out, int out_n) {
    int b = blockIdx.x, tid = threadIdx.x;
    // weight tensors: 4,194,304 uint4 = 4 * (NB_W*256)  -> exactly 4 iters
    if (b < NB_W) {
        conv4(Wg, g_wg, b * 256 + tid, NB_W * 256);
    } else if (b < 2 * NB_W) {
        conv4(Wu, g_wu, (b - NB_W) * 256 + tid, NB_W * 256);
    } else if (b < 2 * NB_W + NB_CONV) {
        // x: 1,048,576 uint4 = 4 * (NB_CONV*256) -> exactly 4 iters
        conv4(hs, g_xh, (b - 2 * NB_W) * 256 + tid, NB_CONV * 256);
    } else if (b < 2 * NB_W + NB_CONV + NB_ROUTE) {
        do_route(hs, Wc, bc, b - 2 * NB_W - NB_CONV, tid);
    } else {
        int zb = b - 2 * NB_W - NB_CONV - NB_ROUTE;
        int n4 = out_n / 4;
        float4 z = make_float4(0.f, 0.f, 0.f, 0.f);
        for (int j = zb * 256 + tid; j < n4; j += NB_ZERO * 256)
            reinterpret_cast<float4*>(out)[j] = z;
    }
}

// =======================================================================
// smem stage layouts (Kc=64, depth-3); both roles use 98304 bytes
// =======================================================================
#define U_A   0                     // 128 rows x 128B = 16384
#define U_BG  16384                 // 64 k-rows x 128B = 8192
#define U_BU  24576
#define U_STAGE 32768

#define D_A   0                     // 128 rows x 128B = 16384
#define D_B   16384                 // 64 k-rows x 256B = 16384
#define D_STAGE 32768
#define F_SMEM (3 * 32768)          // 98304

// grid decode
#define UP_X 33                     // 32 m-tiles + 1 converter slice
#define UP_PER_E (UP_X * 32)        // 1056
#define UP_TOT (UP_PER_E * NE)      // 8448
#define DN_PER_E (32 * 8)           // 256
#define DN_TOT (DN_PER_E * NE)      // 2048
#define F_TOTAL (UP_TOT + DN_TOT)   // 10496

// =======================================================================
// fused MMA kernel: up CTAs first (expert-outermost), then down CTAs that
// spin on per-expert readiness flags. 128 regs -> 2 CTAs/SM.
// =======================================================================
__global__ __launch_bounds__(256, 2)
void fused_mma_kernel(const float* __restrict__ Wd, float* __restrict__ out) {
    extern __shared__ char dsm[];
    __shared__ int stok[128];

    int b = blockIdx.x, tid = threadIdx.x;
    uint32_t sb = smem_u32(dsm);
    int wid = tid >> 5, l = tid & 31;

    if (b < UP_TOT) {
        // ---------------- UP role ----------------
        int ux = b % UP_X, rem = b / UP_X;
        int uy = rem % 32, uz = rem / 32;   // uz = expert

        if (ux == 32) {
            // Wd fp32->fp16 converter slice (32 per expert)
            const int per = (NE * IDIM * DIM / 4) / (NE * 32);   // 16384
            int slice = uz * 32 + uy;
            conv_chunk(Wd, g_wd, slice * per + tid, (slice + 1) * per, 256);
            __threadfence();
            __syncthreads();
            if (tid == 0) atomicAdd(&g_wd_done[uz], 1);
            return;
        }

        int e = uz, m0 = ux * 128, n0 = uy * 64;
        int ne = g_count[e];
        if (m0 >= ne) {
            if (tid == 0) atomicAdd(&g_up_done[e], 1);
            return;
        }
        if (tid < 128) stok[tid] = (m0 + tid < ne) ? g_rows[e * ESTRIDE + m0 + tid] : -1;
        __syncthreads();

        int wm = wid & 3, wn = wid >> 2;

        const __half* WG = g_wg + (size_t)e * DIM * IDIM;
        const __half* WU = g_wu + (size_t)e * DIM * IDIM;

        int lrow = tid >> 3, lch = tid & 7;
        int lar = (l & 7) + 8 * ((l >> 3) & 1);
        int la_ch = l >> 4;
        int ktr = (l & 7) + 8 * ((l >> 3) & 1);
        int ntc = l >> 4;

        float cg[2][4][4], cu[2][4][4];
#pragma unroll
        for (int i = 0; i < 2; i++)
#pragma unroll
            for (int j = 0; j < 4; j++)
#pragma unroll
                for (int q = 0; q < 4; q++) { cg[i][j][q] = 0.f; cu[i][j][q] = 0.f; }

        const int NK = DIM / 64;

        auto load_stage = [&](int kc, int s) {
            uint32_t st = sb + s * U_STAGE;
            int k0 = kc * 64;
#pragma unroll
            for (int it = 0; it < 4; it++) {
                int row = lrow + it * 32;
                int tok = stok[row];
                uint32_t sz = (tok >= 0) ? 16u : 0u;
                size_t go = (tok >= 0) ? ((size_t)tok * DIM + k0 + lch * 8) : 0;
                CPA16(st + U_A + SWZ8(row, lch), g_xh + go, sz);
            }
#pragma unroll
            for (int it = 0; it < 2; it++) {
                int row = lrow + it * 32;     // k row
                size_t go = (size_t)(k0 + row) * IDIM + n0 + lch * 8;
                uint32_t so = SWZ8(row, lch);
                CPA16(st + U_BG + so, WG + go, 16u);
                CPA16(st + U_BU + so, WU + go, 16u);
            }
            CP_COMMIT();
        };

        load_stage(0, 0);
        load_stage(1, 1);

        int s_cur = 0;
        for (int kc = 0; kc < NK; kc++) {
            if (kc + 2 < NK) {
                int s2 = s_cur + 2; if (s2 >= 3) s2 -= 3;
                load_stage(kc + 2, s2);
                CP_WAIT(2);
            } else if (kc + 1 < NK) {
                CP_WAIT(1);
            } else {
                CP_WAIT(0);
            }
            __syncthreads();

            uint32_t st = sb + s_cur * U_STAGE;
#pragma unroll
            for (int ks = 0; ks < 4; ks++) {
                uint32_t ah[2][4];
#pragma unroll
                for (int mf = 0; mf < 2; mf++) {
                    uint32_t row = wm * 32 + mf * 16 + lar;
                    LDSM4(ah[mf][0], ah[mf][1], ah[mf][2], ah[mf][3],
                          st + U_A + SWZ8(row, 2 * ks + la_ch));
                }
#pragma unroll
                for (int p = 0; p < 2; p++) {
                    uint32_t krow = ks * 16 + ktr;
                    uint32_t nch = wn * 4 + 2 * p + ntc;
                    uint32_t bg[2][2], bu[2][2];
                    LDSM4T(bg[0][0], bg[0][1], bg[1][0], bg[1][1],
                           st + U_BG + SWZ8(krow, nch));
                    LDSM4T(bu[0][0], bu[0][1], bu[1][0], bu[1][1],
                           st + U_BU + SWZ8(krow, nch));
#pragma unroll
                    for (int mf = 0; mf < 2; mf++)
#pragma unroll
                        for (int q = 0; q < 2; q++) {
                            int nf = 2 * p + q;
                            MMA16816(cg[mf][nf], ah[mf], bg[q]);
                            MMA16816(cu[mf][nf], ah[mf], bu[q]);
                        }
                }
            }
            __syncthreads();
            if (++s_cur == 3) s_cur = 0;
        }

        __half* hh = g_hh + (size_t)e * ESTRIDE * IDIM;
#pragma unroll
        for (int mf = 0; mf < 2; mf++) {
            int r_lo = m0 + wm * 32 + mf * 16 + (l >> 2);
#pragma unroll
            for (int nf = 0; nf < 4; nf++) {
                int col = n0 + wn * 32 + nf * 8 + 2 * (l & 3);
#pragma unroll
                for (int half_ = 0; half_ < 2; half_++) {
                    int r = r_lo + half_ * 8;
                    if (r >= ne) continue;
                    float gv0 = cg[mf][nf][half_ * 2 + 0], gv1 = cg[mf][nf][half_ * 2 + 1];
                    float uv0 = cu[mf][nf][half_ * 2 + 0], uv1 = cu[mf][nf][half_ * 2 + 1];
                    float h0 = uv0 * gv0 / (1.0f + expf(-gv0));
                    float h1 = uv1 * gv1 / (1.0f + expf(-gv1));
                    __half ph[2] = {__float2half_rn(h0), __float2half_rn(h1)};
                    *reinterpret_cast<uint32_t*>(hh + (size_t)r * IDIM + col) =
                        *reinterpret_cast<uint32_t*>(ph);
                }
            }
        }
        __threadfence();
        __syncthreads();
        if (tid == 0) atomicAdd(&g_up_done[e], 1);

    } else {
        // ---------------- DOWN role ----------------
        int d = b - UP_TOT;
        int dx = d % 32, rem = d / 32;
        int dy = rem % 8, dz = rem / 8;
        int e = dz, m0 = dx * 128, n0 = dy * 128;
        int ne = g_count[e];
        if (m0 >= ne) return;

        // wait for expert e's up tiles + Wd slice
        if (tid == 0) {
            volatile int* pu = &g_up_done[e];
            volatile int* pw = &g_wd_done[e];
            while (*pu < 1024 || *pw < 32) __nanosleep(200);
        }
        __syncthreads();
        __threadfence();

        int wm = wid & 3, wn = wid >> 2;

        const __half* AH = g_hh + (size_t)e * ESTRIDE * IDIM;
        const __half* B  = g_wd + (size_t)e * IDIM * DIM;

        int lrow = tid >> 3, lch = tid & 7;
        int lrow2 = tid >> 4, lch2 = tid & 15;

        int lar = (l & 7) + 8 * ((l >> 3) & 1);
        int la_ch = l >> 4;
        int ktr = (l & 7) + 8 * ((l >> 3) & 1);
        int ntc = l >> 4;

        float c[2][8][4];
#pragma unroll
        for (int i = 0; i < 2; i++)
#pragma unroll
            for (int j = 0; j < 8; j++)
#pragma unroll
                for (int q = 0; q < 4; q++) c[i][j][q] = 0.f;

        const int NK = IDIM / 64;

        auto load_stage = [&](int kc, int s) {
            uint32_t st = sb + s * D_STAGE;
            int k0 = kc * 64;
#pragma unroll
            for (int it = 0; it < 4; it++) {
                int row = lrow + it * 32;
                uint32_t sz = (m0 + row < ne) ? 16u : 0u;
                size_t ga = (m0 + row < ne) ? ((size_t)(m0 + row) * IDIM + k0 + lch * 8) : 0;
                CPA16(st + D_A + SWZ8(row, lch), AH + ga, sz);
            }
#pragma unroll
            for (int it = 0; it < 4; it++) {
                int row = lrow2 + it * 16;    // k row
                size_t gb = (size_t)(k0 + row) * DIM + n0 + lch2 * 8;
                CPA16(st + D_B + SWZ16(row, lch2), B + gb, 16u);
            }
            CP_COMMIT();
        };

        load_stage(0, 0);
        load_stage(1, 1);

        int s_cur = 0;
        for (int kc = 0; kc < NK; kc++) {
            if (kc + 2 < NK) {
                int s2 = s_cur + 2; if (s2 >= 3) s2 -= 3;
                load_stage(kc + 2, s2);
                CP_WAIT(2);
            } else if (kc + 1 < NK) {
                CP_WAIT(1);
            } else {
                CP_WAIT(0);
            }
            __syncthreads();

            uint32_t st = sb + s_cur * D_STAGE;
#pragma unroll
            for (int ks = 0; ks < 4; ks++) {
                uint32_t ah[2][4];
#pragma unroll
                for (int mf = 0; mf < 2; mf++) {
                    uint32_t row = wm * 32 + mf * 16 + lar;
                    LDSM4(ah[mf][0], ah[mf][1], ah[mf][2], ah[mf][3],
                          st + D_A + SWZ8(row, 2 * ks + la_ch));
                }
#pragma unroll
                for (int p = 0; p < 4; p++) {
                    uint32_t krow = ks * 16 + ktr;
                    uint32_t nch = wn * 8 + 2 * p + ntc;
                    uint32_t bh[2][2];
                    LDSM4T(bh[0][0], bh[0][1], bh[1][0], bh[1][1],
                           st + D_B + SWZ16(krow, nch));
#pragma unroll
                    for (int mf = 0; mf < 2; mf++)
#pragma unroll
                        for (int q = 0; q < 2; q++)
                            MMA16816(c[mf][2 * p + q], ah[mf], bh[q]);
                }
            }
            __syncthreads();
            if (++s_cur == 3) s_cur = 0;
        }

#pragma unroll
        for (int mf = 0; mf < 2; mf++) {
            int r_lo = m0 + wm * 32 + mf * 16 + (l >> 2);
#pragma unroll
            for (int half_ = 0; half_ < 2; half_++) {
                int r = r_lo + half_ * 8;
                if (r >= ne) continue;
                int   t = g_rows[e * ESTRIDE + r];
                float w = g_w[e * ESTRIDE + r];
                float* op = out + (size_t)t * DIM;
#pragma unroll
                for (int nf = 0; nf < 8; nf++) {
                    int col = n0 + wn * 64 + nf * 8 + 2 * (l & 3);
                    REDV2(op + col, w * c[mf][nf][half_ * 2 + 0],
                                    w * c[mf][nf][half_ * 2 + 1]);
                }
            }
        }
    }
}

// ---------------- launcher ----------------
extern "C" void kernel_launch(void* const* d_in, const int* in_sizes, int n_in,
                              void* d_out, int out_size) {
    const float* hs = (const float*)d_in[0];
    const float* Wc = (const float*)d_in[1];
    const float* bc = (const float*)d_in[2];
    const float* Wg = (const float*)d_in[3];
    const float* Wu = (const float*)d_in[4];
    const float* Wd = (const float*)d_in[5];
    float* out = (float*)d_out;

    cudaFuncSetAttribute(fused_mma_kernel, cudaFuncAttributeMaxDynamicSharedMemorySize, F_SMEM);

    void* p;
    cudaGetSymbolAddress(&p, g_count);
    cudaMemsetAsync(p, 0, NE * sizeof(int));
    cudaGetSymbolAddress(&p, g_up_done);
    cudaMemsetAsync(p, 0, NE * sizeof(int));
    cudaGetSymbolAddress(&p, g_wd_done);
    cudaMemsetAsync(p, 0, NE * sizeof(int));

    prologue_kernel<<<NB_TOTAL, 256>>>(hs, Wc, bc, Wg, Wu, out, out_size);

    fused_mma_kernel<<<F_TOTAL, 256, F_SMEM>>>(Wd, out);
}